// round 14
// baseline (speedup 1.0000x reference)
#include <cuda_runtime.h>
#include <cuda_fp16.h>
#include <cstdint>

// Problem constants
#define BB 8192
#define DD 1024
#define HH 1024
#define EE 16

#define GM BB
#define GN HH
#define GK 1024
#define BM 128
#define BN 128
#define BKH 64           // k halves per tile (= 128 bytes per row)
#define KTH (GK / BKH)   // 16 k-tiles
#define NSTG 2

#define TILE_BYTES (128 * 128)          // 16 KB (128 rows x 128B)
#define STG_BYTES (2 * TILE_BYTES)      // A + B = 32 KB
#define SMEM_TOTAL (NSTG * STG_BYTES)   // 64 KB
#define EPI_STRIDE 272                  // staging row stride (bytes), conflict-free

// ---------------- scratch (device globals: allocation-free rule) -------------
__device__ __half g_xh [(size_t)BB * DD];         //  16 MB  fp16 x
__device__ __half g_W1h[(size_t)EE * DD * HH];    //  32 MB  W1^T fp16 [E][n][k]
__device__ __half g_W2h[(size_t)EE * HH * HH];    //  32 MB  W2^T fp16 [E][n][k]
__device__ __half g_h1 [(size_t)EE * BB * HH];    // 256 MB  h1 fp16
__device__ float  g_f  [(size_t)BB * EE];         // expert scalars (atomic acc)
__device__ float  g_v  [(size_t)EE * HH];         // folded W2.Wo (fp32, atomic acc)
__device__ float  g_c  [EE];                      // folded b2.Wo + bo

// ---------------- helpers ----------------------------------------------------
__device__ __forceinline__ void cp_async16(uint32_t smem, const void* gmem) {
    asm volatile("cp.async.cg.shared.global [%0], [%1], 16;\n" :: "r"(smem), "l"(gmem));
}
__device__ __forceinline__ void cp_commit() { asm volatile("cp.async.commit_group;\n"); }
template <int N>
__device__ __forceinline__ void cp_wait() { asm volatile("cp.async.wait_group %0;\n" :: "n"(N)); }

__device__ __forceinline__ void ldsm4(uint32_t& r0, uint32_t& r1, uint32_t& r2, uint32_t& r3,
                                      uint32_t addr) {
    asm volatile("ldmatrix.sync.aligned.m8n8.x4.shared.b16 {%0,%1,%2,%3}, [%4];"
                 : "=r"(r0), "=r"(r1), "=r"(r2), "=r"(r3) : "r"(addr));
}
__device__ __forceinline__ void mma_f16(float* d, const uint32_t* a, const uint32_t* b) {
    asm volatile(
        "mma.sync.aligned.m16n8k16.row.col.f32.f16.f16.f32 "
        "{%0,%1,%2,%3}, {%4,%5,%6,%7}, {%8,%9}, {%0,%1,%2,%3};"
        : "+f"(d[0]), "+f"(d[1]), "+f"(d[2]), "+f"(d[3])
        : "r"(a[0]), "r"(a[1]), "r"(a[2]), "r"(a[3]), "r"(b[0]), "r"(b[1]));
}

// ---------------- prep kernels ------------------------------------------------
__global__ void convert_x(const float* __restrict__ x) {
    size_t i = (size_t)blockIdx.x * blockDim.x + threadIdx.x;
    g_xh[i] = __float2half_rn(x[i]);
    if (i < (size_t)BB * EE) g_f[i] = 0.0f;
    if (i < (size_t)EE * HH) g_v[i] = 0.0f;
}

// transpose W1, W2 to [E][n][k] fp16 (vectorized __half2 stores)
// + fused fold of v[e,h]=W2[e,h,:].Wo[e,:] and c[e]=b2[e,:].Wo[e,:]+bo[e]
__global__ void transpose_w(const float* __restrict__ W1, const float* __restrict__ W2,
                            const float* __restrict__ Wo, const float* __restrict__ b2,
                            const float* __restrict__ bo) {
    __shared__ float t1[64][33], t2[64][33];
    const int e  = blockIdx.z;
    const int c0 = blockIdx.x * 32;   // source col (n index)
    const int r0 = blockIdx.y * 64;   // source row (k index)
    const size_t eo = (size_t)e << 20;
    const int tx = threadIdx.x, ty = threadIdx.y;

#pragma unroll
    for (int i = 0; i < 64; i += 8) {
        t1[ty + i][tx] = W1[eo + (size_t)(r0 + ty + i) * 1024 + c0 + tx];
        t2[ty + i][tx] = W2[eo + (size_t)(r0 + ty + i) * 1024 + c0 + tx];
    }
    __syncthreads();

#pragma unroll
    for (int i = 0; i < 32; i += 8) {
        const int row = ty + i;
        size_t o = eo + (size_t)(c0 + row) * 1024 + r0 + 2 * tx;
        *(__half2*)&g_W1h[o] = __floats2half2_rn(t1[2 * tx][row], t1[2 * tx + 1][row]);
        *(__half2*)&g_W2h[o] = __floats2half2_rn(t2[2 * tx][row], t2[2 * tx + 1][row]);
    }

    const float wov = Wo[(size_t)e * HH + c0 + tx];
#pragma unroll
    for (int i = 0; i < 8; i++) {
        const int row = ty * 8 + i;
        float s = t2[row][tx] * wov;
#pragma unroll
        for (int off = 16; off; off >>= 1) s += __shfl_xor_sync(0xFFFFFFFFu, s, off);
        if (tx == 0) atomicAdd(&g_v[(size_t)e * HH + r0 + row], s);
    }

    if (blockIdx.x == 0 && blockIdx.y == 0 && ty == 0) {
        float s = 0.0f;
        for (int i = tx; i < HH; i += 32)
            s += b2[(size_t)e * HH + i] * Wo[(size_t)e * HH + i];
#pragma unroll
        for (int off = 16; off; off >>= 1) s += __shfl_xor_sync(0xFFFFFFFFu, s, off);
        if (tx == 0) g_c[e] = s + bo[e];
    }
}

// ---------------- batched expert GEMM (mma.sync fp16, ldmatrix) ---------------
// STAGE 0: h1[e,b,n] = fp16(sigmoid(x[b,:].W1[e,:,n] + b1[e,n]))
// STAGE 1: f[b,e]   += sum_n relu(h1[e,b,:].W2[e,:,n] + b2[e,n]) * v[e,n]
// CTA 128 threads (2x2 warps), warp tile 64x64, CTA tile 128x128, BK=64 halves.
// NSTG=2 double buffer; 3 CTAs/SM (3 warps/SMSP) with 25% smem slack.
template <int STAGE>
__global__ __launch_bounds__(128, 3) void expert_gemm(const float* __restrict__ bias_all) {
    extern __shared__ char smem[];
    const uint32_t sbase = (uint32_t)__cvta_generic_to_shared(smem);

    const int e  = blockIdx.z;
    const int m0 = blockIdx.y * BM;
    const int n0 = blockIdx.x * BN;

    const __half* A  = (STAGE == 0) ? g_xh : (g_h1 + (size_t)e * BB * GK);
    const __half* Bt = ((STAGE == 0) ? g_W1h : g_W2h) + ((size_t)e << 20);
    const float* bias = bias_all + (size_t)e * HH;

    const int tid  = threadIdx.x;
    const int lane = tid & 31;
    const int warp = tid >> 5;
    const int wm   = warp & 1;   // 2 warps over M (64 rows each)
    const int wn   = warp >> 1;  // 2 warps over N (64 cols each)
    const int ar   = lane >> 2;
    const int ac   = lane & 3;
    const int g    = lane >> 3;  // ldmatrix lane group 0..3
    const int rl   = lane & 7;

    float acc[4][8][4];
#pragma unroll
    for (int mi = 0; mi < 4; mi++)
#pragma unroll
        for (int ni = 0; ni < 8; ni++)
#pragma unroll
            for (int r = 0; r < 4; r++) acc[mi][ni][r] = 0.0f;

    const __half* Agm = A + (size_t)m0 * GK;
    const __half* Bgm = Bt + (size_t)n0 * GK;

    // one part = 1 A chunk + 1 B chunk per thread (8 parts = full 32KB tile)
    auto load_part = [&](int s, int kt, int p) {
        const uint32_t a0 = sbase + s * STG_BYTES;
        const uint32_t b0 = a0 + TILE_BYTES;
        const __half* Ag = Agm + kt * BKH;
        const __half* Bg = Bgm + kt * BKH;
        int j = tid + p * 128;
        int row = j >> 3, c = j & 7;
        uint32_t off = row * 128 + (((c ^ (row & 7)) << 4));
        cp_async16(a0 + off, Ag + (size_t)row * GK + c * 8);
        cp_async16(b0 + off, Bg + (size_t)row * GK + c * 8);
    };

    // precomputed ldmatrix row/col components (64x64 warp tile)
    const int arow = wm * 64 + ((g & 1) << 3) + rl;    // + mi*16
    const int ackg = g >> 1;                           // + ks*2
    const int brow = wn * 64 + ((g >> 1) << 3) + rl;   // + nj*16
    const int bckg = g & 1;                            // + ks*2

    // prologue: k-tile 0 into stage 0
#pragma unroll
    for (int p = 0; p < 8; p++) load_part(0, 0, p);
    cp_commit();

    for (int kt = 0; kt < KTH; ++kt) {
        const int s = kt & 1;
        cp_wait<0>();
        __syncthreads();

        const bool pre = (kt + 1 < KTH);
        const int s2 = s ^ 1;

        const uint32_t aB = sbase + s * STG_BYTES;
        const uint32_t bB = aB + TILE_BYTES;

#pragma unroll
        for (int ks = 0; ks < 4; ++ks) {
            // spread next-tile loads: 2 parts per ks
            if (pre) {
                load_part(s2, kt + 1, 2 * ks);
                load_part(s2, kt + 1, 2 * ks + 1);
            }
            uint32_t afr[4][4];
#pragma unroll
            for (int mi = 0; mi < 4; mi++) {
                int row = arow + mi * 16;
                int ck  = ks * 2 + ackg;
                ldsm4(afr[mi][0], afr[mi][1], afr[mi][2], afr[mi][3],
                      aB + row * 128 + ((ck ^ (row & 7)) << 4));
            }
#pragma unroll
            for (int nj = 0; nj < 4; nj++) {
                uint32_t bfr[2][2];
                int row = brow + nj * 16;
                int ck  = ks * 2 + bckg;
                ldsm4(bfr[0][0], bfr[0][1], bfr[1][0], bfr[1][1],
                      bB + row * 128 + ((ck ^ (row & 7)) << 4));
#pragma unroll
                for (int mi = 0; mi < 4; mi++) {
                    mma_f16(acc[mi][2 * nj],     afr[mi], bfr[0]);
                    mma_f16(acc[mi][2 * nj + 1], afr[mi], bfr[1]);
                }
            }
        }
        cp_commit();
    }

    if (STAGE == 0) {
        // ---- staged epilogue: sigmoid -> smem (conflict-free) -> STG.128 ----
        cp_wait<0>();
        __syncthreads();   // all LDSM done, pipeline smem reusable
#pragma unroll
        for (int mi = 0; mi < 4; mi++) {
            const int lr = wm * 64 + mi * 16 + ar;   // local row (and +8)
#pragma unroll
            for (int ni = 0; ni < 8; ni++) {
                const int lc = wn * 64 + ni * 8 + ac * 2;
                float bv0 = __ldg(&bias[n0 + lc]), bv1 = __ldg(&bias[n0 + lc + 1]);
                float v0 = __fdividef(1.0f, 1.0f + __expf(-(acc[mi][ni][0] + bv0)));
                float v1 = __fdividef(1.0f, 1.0f + __expf(-(acc[mi][ni][1] + bv1)));
                float v2 = __fdividef(1.0f, 1.0f + __expf(-(acc[mi][ni][2] + bv0)));
                float v3 = __fdividef(1.0f, 1.0f + __expf(-(acc[mi][ni][3] + bv1)));
                *(__half2*)(smem + lr * EPI_STRIDE + lc * 2)       = __floats2half2_rn(v0, v1);
                *(__half2*)(smem + (lr + 8) * EPI_STRIDE + lc * 2) = __floats2half2_rn(v2, v3);
            }
        }
        __syncthreads();
        // cooperative coalesced copy: 128 rows x 256B, 16B chunks (2048 / 128 thr)
        __half* C = g_h1 + (size_t)e * BB * HH;
#pragma unroll
        for (int pass = 0; pass < 16; pass++) {
            int chunk = tid + pass * 128;
            int row = chunk >> 4;        // 0..127
            int c16 = chunk & 15;        // 16B chunk within row
            uint4 v = *(const uint4*)(smem + row * EPI_STRIDE + c16 * 16);
            *(uint4*)&C[(size_t)(m0 + row) * HH + n0 + c16 * 8] = v;
        }
    } else {
        // f epilogue: relu(acc + b2[c]) * v[e,c], row-reduce, atomicAdd
        const float* ve = g_v + (size_t)e * HH;
#pragma unroll
        for (int mi = 0; mi < 4; mi++) {
            int r0 = m0 + wm * 64 + mi * 16 + ar;
            float s0 = 0.0f, s1 = 0.0f;
#pragma unroll
            for (int ni = 0; ni < 8; ni++) {
                int c0 = n0 + wn * 64 + ni * 8 + ac * 2;
                float bv0 = __ldg(&bias[c0]), bv1 = __ldg(&bias[c0 + 1]);
                float vv0 = __ldg(&ve[c0]),   vv1 = __ldg(&ve[c0 + 1]);
                s0 += fmaxf(acc[mi][ni][0] + bv0, 0.0f) * vv0
                    + fmaxf(acc[mi][ni][1] + bv1, 0.0f) * vv1;
                s1 += fmaxf(acc[mi][ni][2] + bv0, 0.0f) * vv0
                    + fmaxf(acc[mi][ni][3] + bv1, 0.0f) * vv1;
            }
            s0 += __shfl_xor_sync(0xFFFFFFFFu, s0, 1);
            s0 += __shfl_xor_sync(0xFFFFFFFFu, s0, 2);
            s1 += __shfl_xor_sync(0xFFFFFFFFu, s1, 1);
            s1 += __shfl_xor_sync(0xFFFFFFFFu, s1, 2);
            if (ac == 0) {
                atomicAdd(&g_f[(size_t)r0 * EE + e], s0);
                atomicAdd(&g_f[(size_t)(r0 + 8) * EE + e], s1);
            }
        }
    }
}

// ---------------- gates + final mix -------------------------------------------
__global__ void gate_kernel(const float* __restrict__ x,
                            const float* __restrict__ Wg1, const float* __restrict__ bg1,
                            const float* __restrict__ Wg2, const float* __restrict__ bg2,
                            float* __restrict__ out) {
    __shared__ float sm[8][32][33];
    const int lane = threadIdx.x & 31;
    const int w    = threadIdx.x >> 5;
    const int b    = blockIdx.x * 8 + w;

    const float* xr = x + (size_t)b * DD;
    float a1[16], a2[16];
#pragma unroll
    for (int v = 0; v < 16; v++) { a1[v] = 0.0f; a2[v] = 0.0f; }

    for (int i = 0; i < 32; i++) {
        int d = i * 32 + lane;
        float xv = xr[d];
        const float4* w1 = (const float4*)(Wg1 + (size_t)d * EE);
        const float4* w2 = (const float4*)(Wg2 + (size_t)d * EE);
#pragma unroll
        for (int j = 0; j < 4; j++) {
            float4 v1 = w1[j];
            a1[4 * j + 0] += xv * v1.x; a1[4 * j + 1] += xv * v1.y;
            a1[4 * j + 2] += xv * v1.z; a1[4 * j + 3] += xv * v1.w;
            float4 v2 = w2[j];
            a2[4 * j + 0] += xv * v2.x; a2[4 * j + 1] += xv * v2.y;
            a2[4 * j + 2] += xv * v2.z; a2[4 * j + 3] += xv * v2.w;
        }
    }
#pragma unroll
    for (int v = 0; v < 16; v++) {
        sm[w][v][lane]      = a1[v];
        sm[w][16 + v][lane] = a2[v];
    }
    __syncwarp();
    float z = 0.0f;
#pragma unroll
    for (int t = 0; t < 32; t++) z += sm[w][lane][t];
    z += (lane < 16) ? bg1[lane] : bg2[lane - 16];

    float mx = z;
#pragma unroll
    for (int off = 8; off; off >>= 1) mx = fmaxf(mx, __shfl_xor_sync(0xFFFFFFFFu, mx, off));
    float ez = __expf(z - mx);
    float s = ez;
#pragma unroll
    for (int off = 8; off; off >>= 1) s += __shfl_xor_sync(0xFFFFFFFFu, s, off);
    float g = ez / s;

    float fv = g_f[(size_t)b * EE + (lane & 15)] + g_c[lane & 15];
    float p = g * fv;
#pragma unroll
    for (int off = 8; off; off >>= 1) p += __shfl_xor_sync(0xFFFFFFFFu, p, off);

    if (lane == 0)  out[b] = p;
    if (lane == 16) out[BB + b] = p;
}

// ---------------- launch ------------------------------------------------------
extern "C" void kernel_launch(void* const* d_in, const int* in_sizes, int n_in,
                              void* d_out, int out_size) {
    const float* x   = (const float*)d_in[0];
    const float* W1  = (const float*)d_in[1];
    const float* b1  = (const float*)d_in[2];
    const float* W2  = (const float*)d_in[3];
    const float* b2  = (const float*)d_in[4];
    const float* Wo  = (const float*)d_in[5];
    const float* bo  = (const float*)d_in[6];
    const float* Wg1 = (const float*)d_in[7];
    const float* bg1 = (const float*)d_in[8];
    const float* Wg2 = (const float*)d_in[9];
    const float* bg2 = (const float*)d_in[10];
    float* out = (float*)d_out;

    cudaFuncSetAttribute(expert_gemm<0>, cudaFuncAttributeMaxDynamicSharedMemorySize, SMEM_TOTAL);
    cudaFuncSetAttribute(expert_gemm<1>, cudaFuncAttributeMaxDynamicSharedMemorySize, SMEM_TOTAL);

    convert_x<<<(BB * DD) / 256, 256>>>(x);                        // zeroes g_f, g_v
    transpose_w<<<dim3(32, 16, EE), dim3(32, 8)>>>(W1, W2, Wo, b2, bo);

    dim3 ggrid(GN / BN, GM / BM, EE);                              // (8, 64, 16)
    expert_gemm<0><<<ggrid, 128, SMEM_TOTAL>>>(b1);
    expert_gemm<1><<<ggrid, 128, SMEM_TOTAL>>>(b2);
    gate_kernel<<<BB / 8, 256>>>(x, Wg1, bg1, Wg2, bg2, out);
}

// round 17
// speedup vs baseline: 1.0767x; 1.0767x over previous
#include <cuda_runtime.h>
#include <cuda_fp16.h>
#include <cstdint>

// Problem constants
#define BB 8192
#define DD 1024
#define HH 1024
#define EE 16

#define GM BB
#define GN HH
#define GK 1024
#define BM 128
#define BN 128
#define BKH 64           // k halves per tile (= 128 bytes per row)
#define KTH (GK / BKH)   // 16 k-tiles
#define NSTG 3

#define TILE_BYTES (128 * 128)          // 16 KB (128 rows x 128B)
#define STG_BYTES (2 * TILE_BYTES)      // A + B = 32 KB
#define SMEM_TOTAL (NSTG * STG_BYTES)   // 96 KB
#define EPI_STRIDE 272                  // staging row stride (bytes), conflict-free

// ---------------- scratch (device globals: allocation-free rule) -------------
__device__ __half g_xh [(size_t)BB * DD];         //  16 MB  fp16 x
__device__ __half g_W1h[(size_t)EE * DD * HH];    //  32 MB  W1^T fp16 [E][n][k]
__device__ __half g_W2h[(size_t)EE * HH * HH];    //  32 MB  W2^T fp16 [E][n][k]
__device__ __half g_h1 [(size_t)EE * BB * HH];    // 256 MB  h1 fp16
__device__ float  g_f  [(size_t)BB * EE];         // expert scalars (atomic acc)
__device__ float  g_v  [(size_t)EE * HH];         // folded W2.Wo (fp32, atomic acc)
__device__ float  g_c  [EE];                      // folded b2.Wo + bo

// ---------------- helpers ----------------------------------------------------
__device__ __forceinline__ void cp_async16(uint32_t smem, const void* gmem) {
    asm volatile("cp.async.cg.shared.global [%0], [%1], 16;\n" :: "r"(smem), "l"(gmem));
}
__device__ __forceinline__ void cp_commit() { asm volatile("cp.async.commit_group;\n"); }
template <int N>
__device__ __forceinline__ void cp_wait() { asm volatile("cp.async.wait_group %0;\n" :: "n"(N)); }

__device__ __forceinline__ void ldsm4(uint32_t& r0, uint32_t& r1, uint32_t& r2, uint32_t& r3,
                                      uint32_t addr) {
    asm volatile("ldmatrix.sync.aligned.m8n8.x4.shared.b16 {%0,%1,%2,%3}, [%4];"
                 : "=r"(r0), "=r"(r1), "=r"(r2), "=r"(r3) : "r"(addr));
}
__device__ __forceinline__ void mma_f16(float* d, const uint32_t* a, const uint32_t* b) {
    asm volatile(
        "mma.sync.aligned.m16n8k16.row.col.f32.f16.f16.f32 "
        "{%0,%1,%2,%3}, {%4,%5,%6,%7}, {%8,%9}, {%0,%1,%2,%3};"
        : "+f"(d[0]), "+f"(d[1]), "+f"(d[2]), "+f"(d[3])
        : "r"(a[0]), "r"(a[1]), "r"(a[2]), "r"(a[3]), "r"(b[0]), "r"(b[1]));
}

// sigmoid(z0),sigmoid(z1) packed as half2 via tanh.approx.f16x2:
// sigmoid(z) = 0.5*tanh(z/2) + 0.5   (1 MUFU per 2 elements)
__device__ __forceinline__ __half2 sigmoid2(float z0, float z1) {
    __half2 hz = __floats2half2_rn(z0 * 0.5f, z1 * 0.5f);
    uint32_t t;
    asm("tanh.approx.f16x2 %0, %1;" : "=r"(t) : "r"(*(uint32_t*)&hz));
    const __half2 half05 = __floats2half2_rn(0.5f, 0.5f);
    return __hfma2(*(__half2*)&t, half05, half05);
}

// ---------------- prep kernels ------------------------------------------------
__global__ void convert_x(const float* __restrict__ x) {
    size_t i = (size_t)blockIdx.x * blockDim.x + threadIdx.x;
    g_xh[i] = __float2half_rn(x[i]);
    if (i < (size_t)BB * EE) g_f[i] = 0.0f;
    if (i < (size_t)EE * HH) g_v[i] = 0.0f;
}

// transpose W1, W2 to [E][n][k] fp16 (vectorized __half2 stores)
// + fused fold of v[e,h]=W2[e,h,:].Wo[e,:] and c[e]=b2[e,:].Wo[e,:]+bo[e]
__global__ void transpose_w(const float* __restrict__ W1, const float* __restrict__ W2,
                            const float* __restrict__ Wo, const float* __restrict__ b2,
                            const float* __restrict__ bo) {
    __shared__ float t1[64][33], t2[64][33];
    const int e  = blockIdx.z;
    const int c0 = blockIdx.x * 32;   // source col (n index)
    const int r0 = blockIdx.y * 64;   // source row (k index)
    const size_t eo = (size_t)e << 20;
    const int tx = threadIdx.x, ty = threadIdx.y;

#pragma unroll
    for (int i = 0; i < 64; i += 8) {
        t1[ty + i][tx] = W1[eo + (size_t)(r0 + ty + i) * 1024 + c0 + tx];
        t2[ty + i][tx] = W2[eo + (size_t)(r0 + ty + i) * 1024 + c0 + tx];
    }
    __syncthreads();

#pragma unroll
    for (int i = 0; i < 32; i += 8) {
        const int row = ty + i;
        size_t o = eo + (size_t)(c0 + row) * 1024 + r0 + 2 * tx;
        *(__half2*)&g_W1h[o] = __floats2half2_rn(t1[2 * tx][row], t1[2 * tx + 1][row]);
        *(__half2*)&g_W2h[o] = __floats2half2_rn(t2[2 * tx][row], t2[2 * tx + 1][row]);
    }

    const float wov = Wo[(size_t)e * HH + c0 + tx];
#pragma unroll
    for (int i = 0; i < 8; i++) {
        const int row = ty * 8 + i;
        float s = t2[row][tx] * wov;
#pragma unroll
        for (int off = 16; off; off >>= 1) s += __shfl_xor_sync(0xFFFFFFFFu, s, off);
        if (tx == 0) atomicAdd(&g_v[(size_t)e * HH + r0 + row], s);
    }

    if (blockIdx.x == 0 && blockIdx.y == 0 && ty == 0) {
        float s = 0.0f;
        for (int i = tx; i < HH; i += 32)
            s += b2[(size_t)e * HH + i] * Wo[(size_t)e * HH + i];
#pragma unroll
        for (int off = 16; off; off >>= 1) s += __shfl_xor_sync(0xFFFFFFFFu, s, off);
        if (tx == 0) g_c[e] = s + bo[e];
    }
}

// ---------------- batched expert GEMM (mma.sync fp16, ldmatrix) ---------------
// STAGE 0: h1[e,b,n] = fp16(sigmoid(x[b,:].W1[e,:,n] + b1[e,n]))
//          epilogue: tanh.approx.f16x2 sigmoid -> smem staging -> STG.128
// STAGE 1: f[b,e]   += sum_n relu(h1[e,b,:].W2[e,:,n] + b2[e,n]) * v[e,n]
// CTA 256 threads (4x2 warps), warp tile 32x64, CTA tile 128x128, BK=64 halves.
template <int STAGE>
__global__ __launch_bounds__(256, 2) void expert_gemm(const float* __restrict__ bias_all) {
    extern __shared__ char smem[];
    const uint32_t sbase = (uint32_t)__cvta_generic_to_shared(smem);

    const int e  = blockIdx.z;
    const int m0 = blockIdx.y * BM;
    const int n0 = blockIdx.x * BN;

    const __half* A  = (STAGE == 0) ? g_xh : (g_h1 + (size_t)e * BB * GK);
    const __half* Bt = ((STAGE == 0) ? g_W1h : g_W2h) + ((size_t)e << 20);
    const float* bias = bias_all + (size_t)e * HH;

    const int tid  = threadIdx.x;
    const int lane = tid & 31;
    const int warp = tid >> 5;
    const int wm   = warp & 3;   // 4 warps over M (32 rows each)
    const int wn   = warp >> 2;  // 2 warps over N (64 cols each)
    const int ar   = lane >> 2;
    const int ac   = lane & 3;
    const int g    = lane >> 3;  // ldmatrix lane group 0..3
    const int rl   = lane & 7;

    float acc[2][8][4];
#pragma unroll
    for (int mi = 0; mi < 2; mi++)
#pragma unroll
        for (int ni = 0; ni < 8; ni++)
#pragma unroll
            for (int r = 0; r < 4; r++) acc[mi][ni][r] = 0.0f;

    const __half* Agm = A + (size_t)m0 * GK;
    const __half* Bgm = Bt + (size_t)n0 * GK;

    // one part = 1 A chunk + 1 B chunk per thread (4 parts = full tile)
    auto load_part = [&](int s, int kt, int p) {
        const uint32_t a0 = sbase + s * STG_BYTES;
        const uint32_t b0 = a0 + TILE_BYTES;
        const __half* Ag = Agm + kt * BKH;
        const __half* Bg = Bgm + kt * BKH;
        int j = tid + p * 256;
        int row = j >> 3, c = j & 7;
        uint32_t off = row * 128 + (((c ^ (row & 7)) << 4));
        cp_async16(a0 + off, Ag + (size_t)row * GK + c * 8);
        cp_async16(b0 + off, Bg + (size_t)row * GK + c * 8);
    };

    // precomputed ldmatrix row/col components
    const int arow = wm * 32 + ((g & 1) << 3) + rl;    // + mi*16
    const int ackg = g >> 1;                           // + ks*2
    const int brow = wn * 64 + ((g >> 1) << 3) + rl;   // + nj*16
    const int bckg = g & 1;                            // + ks*2

#pragma unroll
    for (int s = 0; s < NSTG - 1; s++) {
#pragma unroll
        for (int p = 0; p < 4; p++) load_part(s, s, p);
        cp_commit();
    }

    for (int kt = 0; kt < KTH; ++kt) {
        const int s = kt % NSTG;
        cp_wait<NSTG - 2>();
        __syncthreads();                 // single barrier per k-tile

        const bool pre = (kt + NSTG - 1 < KTH);
        const int s2   = (kt + NSTG - 1) % NSTG;
        const int kt2  = kt + NSTG - 1;

        const uint32_t aB = sbase + s * STG_BYTES;
        const uint32_t bB = aB + TILE_BYTES;

#pragma unroll
        for (int ks = 0; ks < 4; ++ks) {
            if (pre) load_part(s2, kt2, ks);   // spread cp.async across ks
            uint32_t afr[2][4], bfr[8][2];
#pragma unroll
            for (int mi = 0; mi < 2; mi++) {
                int row = arow + mi * 16;
                int ck  = ks * 2 + ackg;
                ldsm4(afr[mi][0], afr[mi][1], afr[mi][2], afr[mi][3],
                      aB + row * 128 + ((ck ^ (row & 7)) << 4));
            }
#pragma unroll
            for (int nj = 0; nj < 4; nj++) {
                int row = brow + nj * 16;
                int ck  = ks * 2 + bckg;
                ldsm4(bfr[2 * nj][0], bfr[2 * nj][1],
                      bfr[2 * nj + 1][0], bfr[2 * nj + 1][1],
                      bB + row * 128 + ((ck ^ (row & 7)) << 4));
            }
#pragma unroll
            for (int mi = 0; mi < 2; mi++)
#pragma unroll
                for (int ni = 0; ni < 8; ni++)
                    mma_f16(acc[mi][ni], afr[mi], bfr[ni]);
        }
        cp_commit();
    }

    if (STAGE == 0) {
        // ---- staged epilogue: tanh-sigmoid -> smem (conflict-free) -> STG.128
        cp_wait<0>();
        __syncthreads();   // all LDSM done, pipeline smem reusable
#pragma unroll
        for (int mi = 0; mi < 2; mi++) {
            const int lr = wm * 32 + mi * 16 + ar;   // local row (and +8)
#pragma unroll
            for (int ni = 0; ni < 8; ni++) {
                const int lc = wn * 64 + ni * 8 + ac * 2;
                float bv0 = __ldg(&bias[n0 + lc]), bv1 = __ldg(&bias[n0 + lc + 1]);
                *(__half2*)(smem + lr * EPI_STRIDE + lc * 2) =
                    sigmoid2(acc[mi][ni][0] + bv0, acc[mi][ni][1] + bv1);
                *(__half2*)(smem + (lr + 8) * EPI_STRIDE + lc * 2) =
                    sigmoid2(acc[mi][ni][2] + bv0, acc[mi][ni][3] + bv1);
            }
        }
        __syncthreads();
        // cooperative coalesced copy: 128 rows x 256B, 16B chunks
        __half* C = g_h1 + (size_t)e * BB * HH;
#pragma unroll
        for (int pass = 0; pass < 8; pass++) {
            int chunk = tid + pass * 256;
            int row = chunk >> 4;        // 0..127
            int c16 = chunk & 15;        // 16B chunk within row
            uint4 v = *(const uint4*)(smem + row * EPI_STRIDE + c16 * 16);
            *(uint4*)&C[(size_t)(m0 + row) * HH + n0 + c16 * 8] = v;
        }
    } else {
        // f epilogue: relu(acc + b2[c]) * v[e,c], row-reduce, atomicAdd
        const float* ve = g_v + (size_t)e * HH;
#pragma unroll
        for (int mi = 0; mi < 2; mi++) {
            int r0 = m0 + wm * 32 + mi * 16 + ar;
            float s0 = 0.0f, s1 = 0.0f;
#pragma unroll
            for (int ni = 0; ni < 8; ni++) {
                int c0 = n0 + wn * 64 + ni * 8 + ac * 2;
                float bv0 = __ldg(&bias[c0]), bv1 = __ldg(&bias[c0 + 1]);
                float vv0 = __ldg(&ve[c0]),   vv1 = __ldg(&ve[c0 + 1]);
                s0 += fmaxf(acc[mi][ni][0] + bv0, 0.0f) * vv0
                    + fmaxf(acc[mi][ni][1] + bv1, 0.0f) * vv1;
                s1 += fmaxf(acc[mi][ni][2] + bv0, 0.0f) * vv0
                    + fmaxf(acc[mi][ni][3] + bv1, 0.0f) * vv1;
            }
            s0 += __shfl_xor_sync(0xFFFFFFFFu, s0, 1);
            s0 += __shfl_xor_sync(0xFFFFFFFFu, s0, 2);
            s1 += __shfl_xor_sync(0xFFFFFFFFu, s1, 1);
            s1 += __shfl_xor_sync(0xFFFFFFFFu, s1, 2);
            if (ac == 0) {
                atomicAdd(&g_f[(size_t)r0 * EE + e], s0);
                atomicAdd(&g_f[(size_t)(r0 + 8) * EE + e], s1);
            }
        }
    }
}

// ---------------- gates + final mix -------------------------------------------
__global__ void gate_kernel(const float* __restrict__ x,
                            const float* __restrict__ Wg1, const float* __restrict__ bg1,
                            const float* __restrict__ Wg2, const float* __restrict__ bg2,
                            float* __restrict__ out) {
    __shared__ float sm[8][32][33];
    const int lane = threadIdx.x & 31;
    const int w    = threadIdx.x >> 5;
    const int b    = blockIdx.x * 8 + w;

    const float* xr = x + (size_t)b * DD;
    float a1[16], a2[16];
#pragma unroll
    for (int v = 0; v < 16; v++) { a1[v] = 0.0f; a2[v] = 0.0f; }

    for (int i = 0; i < 32; i++) {
        int d = i * 32 + lane;
        float xv = xr[d];
        const float4* w1 = (const float4*)(Wg1 + (size_t)d * EE);
        const float4* w2 = (const float4*)(Wg2 + (size_t)d * EE);
#pragma unroll
        for (int j = 0; j < 4; j++) {
            float4 v1 = w1[j];
            a1[4 * j + 0] += xv * v1.x; a1[4 * j + 1] += xv * v1.y;
            a1[4 * j + 2] += xv * v1.z; a1[4 * j + 3] += xv * v1.w;
            float4 v2 = w2[j];
            a2[4 * j + 0] += xv * v2.x; a2[4 * j + 1] += xv * v2.y;
            a2[4 * j + 2] += xv * v2.z; a2[4 * j + 3] += xv * v2.w;
        }
    }
#pragma unroll
    for (int v = 0; v < 16; v++) {
        sm[w][v][lane]      = a1[v];
        sm[w][16 + v][lane] = a2[v];
    }
    __syncwarp();
    float z = 0.0f;
#pragma unroll
    for (int t = 0; t < 32; t++) z += sm[w][lane][t];
    z += (lane < 16) ? bg1[lane] : bg2[lane - 16];

    float mx = z;
#pragma unroll
    for (int off = 8; off; off >>= 1) mx = fmaxf(mx, __shfl_xor_sync(0xFFFFFFFFu, mx, off));
    float ez = __expf(z - mx);
    float s = ez;
#pragma unroll
    for (int off = 8; off; off >>= 1) s += __shfl_xor_sync(0xFFFFFFFFu, s, off);
    float g = ez / s;

    float fv = g_f[(size_t)b * EE + (lane & 15)] + g_c[lane & 15];
    float p = g * fv;
#pragma unroll
    for (int off = 8; off; off >>= 1) p += __shfl_xor_sync(0xFFFFFFFFu, p, off);

    if (lane == 0)  out[b] = p;
    if (lane == 16) out[BB + b] = p;
}

// ---------------- launch ------------------------------------------------------
extern "C" void kernel_launch(void* const* d_in, const int* in_sizes, int n_in,
                              void* d_out, int out_size) {
    const float* x   = (const float*)d_in[0];
    const float* W1  = (const float*)d_in[1];
    const float* b1  = (const float*)d_in[2];
    const float* W2  = (const float*)d_in[3];
    const float* b2  = (const float*)d_in[4];
    const float* Wo  = (const float*)d_in[5];
    const float* bo  = (const float*)d_in[6];
    const float* Wg1 = (const float*)d_in[7];
    const float* bg1 = (const float*)d_in[8];
    const float* Wg2 = (const float*)d_in[9];
    const float* bg2 = (const float*)d_in[10];
    float* out = (float*)d_out;

    cudaFuncSetAttribute(expert_gemm<0>, cudaFuncAttributeMaxDynamicSharedMemorySize, SMEM_TOTAL);
    cudaFuncSetAttribute(expert_gemm<1>, cudaFuncAttributeMaxDynamicSharedMemorySize, SMEM_TOTAL);

    convert_x<<<(BB * DD) / 256, 256>>>(x);                        // zeroes g_f, g_v
    transpose_w<<<dim3(32, 16, EE), dim3(32, 8)>>>(W1, W2, Wo, b2, bo);

    dim3 ggrid(GN / BN, GM / BM, EE);                              // (8, 64, 16)
    expert_gemm<0><<<ggrid, 256, SMEM_TOTAL>>>(b1);
    expert_gemm<1><<<ggrid, 256, SMEM_TOTAL>>>(b2);
    gate_kernel<<<BB / 8, 256>>>(x, Wg1, bg1, Wg2, bg2, out);
}